// round 10
// baseline (speedup 1.0000x reference)
#include <cuda_runtime.h>
#include <cuda_bf16.h>
#include <cstdint>

#define NN   116
#define FIN  116
#define HIDD 256
#define RB   256                        // tile row bytes (128 bf16)
#define TILEB (128 * RB)                // 32768
#define NTHR 512

// swizzle for 256B-pitch tiles: spreads row%8 across banks, keeps 16B units
#define SWZ(o) ((uint32_t)(o) ^ (((uint32_t)(o) >> 4) & 0x70u))

// ---- SMEM byte offsets (per CTA total 113664 -> 2 CTAs/SM) ----
#define OFF_T1    0                        // x tile -> sx tile (tail scratch later)
#define OFF_T2    TILEB                    // sup tile
#define OFF_T3    (2 * TILEB)              // W1^T half (re-staged per half)
#define OFF_W2    (3 * TILEB)              // 256*4 f32 = 4096
#define OFF_B1V   (OFF_W2 + 4096)          // 256 f32
#define OFF_Z     (OFF_B1V + 1024)         // 128*4 f32 = 2048
#define OFF_ZP    (OFF_Z + 2048)           // 4*128*4 f32 = 8192 (permanent)
#define SMEM_BYTES (OFF_ZP + 8192)         // 113664

// tail scratch overlaid in T1 (sx dead after GEMM_B)
#define OFF_FLAT  OFF_T1                   // 512 f32 (464 + zero pad)
#define OFF_RP    (OFF_FLAT + 2048)        // 512 f32
#define OFF_R     (OFF_RP + 2048)          // 64 f32
#define OFF_RED   (OFF_R + 256)            // 16 f32

// pre-rounded, pre-swizzled W1^T tile images: [half][128 rows h'][128 cols f] bf16
__device__ unsigned char g_w1[2 * TILEB];
// pre-transposed Wr1^T: [64 rows j][512 cols i] f32 (i >= 464 zero)
__device__ float g_wr1t[64 * 512];

__device__ __forceinline__ uint32_t smem_u32(const void* p) {
    uint32_t a;
    asm("{ .reg .u64 t; cvta.to.shared.u64 t, %1; cvt.u32.u64 %0, t; }" : "=r"(a) : "l"(p));
    return a;
}
__device__ __forceinline__ uint32_t pack_bf16(float a, float b) {
    __nv_bfloat162 v = __float22bfloat162_rn(make_float2(a, b));
    return *(uint32_t*)&v;
}
__device__ __forceinline__ float bf_lo(uint32_t w) {
    return __bfloat162float(__ushort_as_bfloat16((unsigned short)(w & 0xffff)));
}
__device__ __forceinline__ float bf_hi(uint32_t w) {
    return __bfloat162float(__ushort_as_bfloat16((unsigned short)(w >> 16)));
}

__device__ __forceinline__ void cpasync16(uint32_t s, const void* g) {
    asm volatile("cp.async.cg.shared.global [%0], [%1], 16;" :: "r"(s), "l"(g));
}
#define CP_COMMIT() asm volatile("cp.async.commit_group;")
#define CP_WAIT0()  asm volatile("cp.async.wait_group 0;")

#define LDSM_X4(r0, r1, r2, r3, addr) \
    asm volatile("ldmatrix.sync.aligned.m8n8.x4.shared.b16 {%0,%1,%2,%3}, [%4];" \
        : "=r"(r0), "=r"(r1), "=r"(r2), "=r"(r3) : "r"(addr))
#define LDSM_X4T(r0, r1, r2, r3, addr) \
    asm volatile("ldmatrix.sync.aligned.m8n8.x4.trans.shared.b16 {%0,%1,%2,%3}, [%4];" \
        : "=r"(r0), "=r"(r1), "=r"(r2), "=r"(r3) : "r"(addr))

__device__ __forceinline__ void mma16816(float* d, uint32_t a0, uint32_t a1,
                                         uint32_t a2, uint32_t a3,
                                         uint32_t b0, uint32_t b1) {
    asm volatile(
        "mma.sync.aligned.m16n8k16.row.col.f32.bf16.bf16.f32 "
        "{%0,%1,%2,%3}, {%4,%5,%6,%7}, {%8,%9}, {%0,%1,%2,%3};"
        : "+f"(d[0]), "+f"(d[1]), "+f"(d[2]), "+f"(d[3])
        : "r"(a0), "r"(a1), "r"(a2), "r"(a3), "r"(b0), "r"(b1));
}

// GEMM, warp tile 32x32, B stored K-major [k][n]: trans LDSM for B (GEMM_A)
__device__ __forceinline__ void mma32(float acc[2][4][4],
                                      uint32_t aTile, uint32_t bTile,
                                      int r0, int c0, int lane) {
    const int row_in = (lane & 7) | (((lane >> 3) & 1) << 3);
    const int col_in = (lane >> 4) << 3;
    const uint32_t aRel0 = (uint32_t)((r0 + row_in) * RB + col_in * 2);
    const uint32_t aRel1 = aRel0 + 16 * RB;
    const uint32_t mA0 = (aRel0 >> 4) & 0x70u;
    const uint32_t mA1 = (aRel1 >> 4) & 0x70u;
    const uint32_t bRel0 = (uint32_t)(row_in * RB + (c0 + col_in) * 2);
    const uint32_t bRel1 = bRel0 + 32;
    uint32_t b0 = bTile + SWZ(bRel0);
    uint32_t b1 = bTile + SWZ(bRel1);
    #pragma unroll
    for (int k = 0; k < 8; ++k) {
        const uint32_t ca = (uint32_t)(k * 32);
        uint32_t a0, a1, a2, a3, a4, a5, a6, a7;
        LDSM_X4(a0, a1, a2, a3, aTile + ((aRel0 + ca) ^ mA0));
        LDSM_X4(a4, a5, a6, a7, aTile + ((aRel1 + ca) ^ mA1));
        uint32_t p0, p1, p2, p3, q0, q1, q2, q3;
        LDSM_X4T(p0, p1, p2, p3, b0);
        LDSM_X4T(q0, q1, q2, q3, b1);
        mma16816(acc[0][0], a0, a1, a2, a3, p0, p1);
        mma16816(acc[0][1], a0, a1, a2, a3, p2, p3);
        mma16816(acc[0][2], a0, a1, a2, a3, q0, q1);
        mma16816(acc[0][3], a0, a1, a2, a3, q2, q3);
        mma16816(acc[1][0], a4, a5, a6, a7, p0, p1);
        mma16816(acc[1][1], a4, a5, a6, a7, p2, p3);
        mma16816(acc[1][2], a4, a5, a6, a7, q0, q1);
        mma16816(acc[1][3], a4, a5, a6, a7, q2, q3);
        b0 += 16 * RB;      // +16 k-rows (mask bits invariant)
        b1 += 16 * RB;
    }
}

// GEMM, warp tile 32x32, B stored transposed [n][k]: NON-trans LDSM for B (GEMM_B)
__device__ __forceinline__ void mma32_bt(float acc[2][4][4],
                                         uint32_t aTile, uint32_t bTile,
                                         int r0, int c0, int lane) {
    const int row_in = (lane & 7) | (((lane >> 3) & 1) << 3);
    const int col_in = (lane >> 4) << 3;
    const uint32_t aRel0 = (uint32_t)((r0 + row_in) * RB + col_in * 2);
    const uint32_t aRel1 = aRel0 + 16 * RB;
    const uint32_t mA0 = (aRel0 >> 4) & 0x70u;
    const uint32_t mA1 = (aRel1 >> 4) & 0x70u;
    const uint32_t bRel0 = (uint32_t)((c0 + row_in) * RB + col_in * 2);
    const uint32_t bRel1 = bRel0 + 16 * RB;
    const uint32_t mB0 = (bRel0 >> 4) & 0x70u;
    const uint32_t mB1 = (bRel1 >> 4) & 0x70u;
    #pragma unroll
    for (int k = 0; k < 8; ++k) {
        const uint32_t ca = (uint32_t)(k * 32);
        uint32_t a0, a1, a2, a3, a4, a5, a6, a7;
        LDSM_X4(a0, a1, a2, a3, aTile + ((aRel0 + ca) ^ mA0));
        LDSM_X4(a4, a5, a6, a7, aTile + ((aRel1 + ca) ^ mA1));
        uint32_t p0, p1, p2, p3, q0, q1, q2, q3;
        LDSM_X4(p0, p1, p2, p3, bTile + ((bRel0 + ca) ^ mB0));
        LDSM_X4(q0, q1, q2, q3, bTile + ((bRel1 + ca) ^ mB1));
        // non-trans mats of B^T: p0=[n0-7,k0-7] p1=[n8-15,k0-7] p2=[n0-7,k8-15] p3=[n8-15,k8-15]
        mma16816(acc[0][0], a0, a1, a2, a3, p0, p2);
        mma16816(acc[0][1], a0, a1, a2, a3, p1, p3);
        mma16816(acc[0][2], a0, a1, a2, a3, q0, q2);
        mma16816(acc[0][3], a0, a1, a2, a3, q1, q3);
        mma16816(acc[1][0], a4, a5, a6, a7, p0, p2);
        mma16816(acc[1][1], a4, a5, a6, a7, p1, p3);
        mma16816(acc[1][2], a4, a5, a6, a7, q0, q2);
        mma16816(acc[1][3], a4, a5, a6, a7, q1, q3);
    }
}

// ---- prep: W1^T [h'][f] into pre-swizzled global bf16 tile images (idempotent) ----
__global__ void prep_w1(const float* __restrict__ W1) {
    int idx = blockIdx.x * blockDim.x + threadIdx.x;
    if (idx >= 2 * 128 * 128) return;
    int half = idx >> 14;
    int rem  = idx & 16383;
    int r = rem >> 7, c = rem & 127;          // r = h' (row), c = f (col)
    float v = (c < FIN) ? W1[c * HIDD + half * 128 + r] : 0.f;
    uint32_t off = SWZ((uint32_t)(r * RB + c * 2));
    *(__nv_bfloat16*)(g_w1 + half * TILEB + off) = __float2bfloat16_rn(v);
}

// ---- prep: Wr1^T [j][i] f32, i padded to 512 with zeros (idempotent) ----
__global__ void prep_wr1(const float* __restrict__ Wr1) {
    int idx = blockIdx.x * blockDim.x + threadIdx.x;
    if (idx >= 64 * 512) return;
    int j = idx >> 9, i = idx & 511;
    g_wr1t[idx] = (i < 464) ? Wr1[(size_t)i * 64 + j] : 0.f;
}

extern __shared__ char smc[];

__global__ void __launch_bounds__(NTHR, 2) gcn_mma(
    const float* __restrict__ x,   const float* __restrict__ sup,
    const float* __restrict__ W1,  const float* __restrict__ b1,
    const float* __restrict__ W2,  const float* __restrict__ b2,
    const float* __restrict__ Wr1, const float* __restrict__ br1,
    const float* __restrict__ Wr2, const float* __restrict__ br2,
    float* __restrict__ out)
{
    const int tid  = threadIdx.x;
    const int b    = blockIdx.x;
    const int lane = tid & 31;
    const int warp = tid >> 5;            // 0..15
    const int r0   = (warp >> 2) * 32;    // 4 row blocks
    const int c0   = (warp & 3) * 32;     // 4 col blocks
    const int wc   = warp & 3;

    float* s_w2   = (float*)(smc + OFF_W2);
    float* s_b1   = (float*)(smc + OFF_B1V);
    float* s_z    = (float*)(smc + OFF_Z);
    float* s_zp   = (float*)(smc + OFF_ZP);
    float* s_flat = (float*)(smc + OFF_FLAT);
    float* s_rp   = (float*)(smc + OFF_RP);
    float* s_r    = (float*)(smc + OFF_R);
    float* s_red  = (float*)(smc + OFF_RED);

    const uint32_t su = smem_u32(smc);

    // prefetch W1^T half0 into T3 via cp.async — hidden behind convert + GEMM_A
    for (int i = tid; i < TILEB / 16; i += NTHR)
        cpasync16(su + OFF_T3 + i * 16, g_w1 + i * 16);
    CP_COMMIT();

    // zero x/sup tiles + zp + preload small weights
    for (int i = tid; i < (2 * TILEB) / 16; i += NTHR)
        ((uint4*)(smc + OFF_T1))[i] = make_uint4(0, 0, 0, 0);
    for (int i = tid; i < 2048; i += NTHR) s_zp[i] = 0.f;
    for (int i = tid; i < HIDD * 4; i += NTHR) s_w2[i] = W2[i];
    for (int i = tid; i < HIDD; i += NTHR)     s_b1[i] = b1[i];
    __syncthreads();

    // load + convert x[b], sup[b] -> bf16 swizzled tiles [m][k]
    const float* xb = x   + (size_t)b * NN * FIN;
    const float* sb = sup + (size_t)b * NN * NN;
    for (int q = tid; q < NN * 29; q += NTHR) {
        int m = q / 29, c4 = (q % 29) * 4;
        uint32_t off = SWZ((uint32_t)(m * RB + c4 * 2));
        float4 vx = *(const float4*)(xb + m * FIN + c4);
        uint2 w;
        w.x = pack_bf16(vx.x, vx.y);
        w.y = pack_bf16(vx.z, vx.w);
        *(uint2*)(smc + OFF_T1 + off) = w;
        float4 vs = *(const float4*)(sb + m * NN + c4);
        w.x = pack_bf16(vs.x, vs.y);
        w.y = pack_bf16(vs.z, vs.w);
        *(uint2*)(smc + OFF_T2 + off) = w;
    }
    __syncthreads();

    // ---- GEMM_A: sx = sup @ x  (A = T2, B = T1 K-major, trans LDSM) ----
    {
        float acc[2][4][4];
        #pragma unroll
        for (int i = 0; i < 2; i++)
            #pragma unroll
            for (int j = 0; j < 4; j++)
                #pragma unroll
                for (int d = 0; d < 4; d++) acc[i][j][d] = 0.f;

        mma32(acc, su + OFF_T2, su + OFF_T1, r0, c0, lane);
        __syncthreads();   // all x reads done before overwrite

        // store sx as bf16 into T1 ([n][f] layout = A of GEMM_B)
        int grow = lane >> 2, gcol = (lane & 3) * 2;
        #pragma unroll
        for (int i = 0; i < 2; i++) {
            #pragma unroll
            for (int j = 0; j < 4; j++) {
                int rr = r0 + i * 16 + grow;
                int cc = c0 + j * 8 + gcol;
                *(uint32_t*)(smc + OFF_T1 + SWZ((uint32_t)(rr * RB + cc * 2))) =
                    pack_bf16(acc[i][j][0], acc[i][j][1]);
                *(uint32_t*)(smc + OFF_T1 + SWZ((uint32_t)((rr + 8) * RB + cc * 2))) =
                    pack_bf16(acc[i][j][2], acc[i][j][3]);
            }
        }
    }
    CP_WAIT0();      // W1^T half0 landed
    __syncthreads();

    for (int half = 0; half < 2; ++half) {
        // ---- GEMM_B: h1_half = sx @ W1half (A = T1, B = T3 = W1^T, non-trans) ----
        float acc[2][4][4];
        #pragma unroll
        for (int i = 0; i < 2; i++)
            #pragma unroll
            for (int j = 0; j < 4; j++)
                #pragma unroll
                for (int d = 0; d < 4; d++) acc[i][j][d] = 0.f;

        mma32_bt(acc, su + OFF_T1, su + OFF_T3, r0, c0, lane);

        // restage W1^T half1 NOW (T3 reads done after barrier); overlaps epilogue
        if (half == 0) {
            __syncthreads();   // all warps' T3 reads done
            for (int i = tid; i < TILEB / 16; i += NTHR)
                cpasync16(su + OFF_T3 + i * 16, g_w1 + TILEB + i * 16);
            CP_COMMIT();
        }

        // epilogue: relu(h1 + b1) contracted with W2 -> zacc -> s_zp
        {
            float zacc[4][4];
            #pragma unroll
            for (int s = 0; s < 4; s++)
                #pragma unroll
                for (int o = 0; o < 4; o++) zacc[s][o] = 0.f;
            int gcol = (lane & 3) * 2;
            #pragma unroll
            for (int i = 0; i < 2; i++) {
                #pragma unroll
                for (int j = 0; j < 4; j++) {
                    int h = half * 128 + c0 + j * 8 + gcol;
                    float b1a = s_b1[h], b1b = s_b1[h + 1];
                    float4 wa = *(const float4*)&s_w2[h * 4];
                    float4 wb = *(const float4*)&s_w2[(h + 1) * 4];
                    float v0 = fmaxf(acc[i][j][0] + b1a, 0.f);
                    float v1 = fmaxf(acc[i][j][1] + b1b, 0.f);
                    float v2 = fmaxf(acc[i][j][2] + b1a, 0.f);
                    float v3 = fmaxf(acc[i][j][3] + b1b, 0.f);
                    zacc[i*2+0][0] += v0 * wa.x + v1 * wb.x;
                    zacc[i*2+0][1] += v0 * wa.y + v1 * wb.y;
                    zacc[i*2+0][2] += v0 * wa.z + v1 * wb.z;
                    zacc[i*2+0][3] += v0 * wa.w + v1 * wb.w;
                    zacc[i*2+1][0] += v2 * wa.x + v3 * wb.x;
                    zacc[i*2+1][1] += v2 * wa.y + v3 * wb.y;
                    zacc[i*2+1][2] += v2 * wa.z + v3 * wb.z;
                    zacc[i*2+1][3] += v2 * wa.w + v3 * wb.w;
                }
            }
            // reduce over the 4 lanes sharing the same rows, accumulate to zp
            #pragma unroll
            for (int s = 0; s < 4; s++) {
                #pragma unroll
                for (int o = 0; o < 4; o++) {
                    float v = zacc[s][o];
                    v += __shfl_xor_sync(0xffffffffu, v, 1);
                    v += __shfl_xor_sync(0xffffffffu, v, 2);
                    zacc[s][o] = v;
                }
            }
            if ((lane & 3) == 0) {
                #pragma unroll
                for (int s = 0; s < 4; s++) {
                    int rr = r0 + (s >> 1) * 16 + (lane >> 2) + (s & 1) * 8;
                    #pragma unroll
                    for (int o = 0; o < 4; o++)
                        s_zp[(wc * 128 + rr) * 4 + o] += zacc[s][o];
                }
            }
        }

        if (half == 0) {
            CP_WAIT0();      // W1^T half1 landed (copy overlapped the epilogue)
            __syncthreads();
        }
    }
    __syncthreads();   // GEMMs done; T1 becomes tail scratch

    // z[n][o] = sum over the 4 column-group partials
    {
        int n = tid >> 2, o = tid & 3;   // exactly 512 items
        s_z[n * 4 + o] = s_zp[(0 * 128 + n) * 4 + o] + s_zp[(1 * 128 + n) * 4 + o]
                       + s_zp[(2 * 128 + n) * 4 + o] + s_zp[(3 * 128 + n) * 4 + o];
    }
    __syncthreads();

    // h2 = relu(sup @ z + b2) -> flat[464], pad to 512 with zeros
    if (tid < NN * 4) {
        int n = tid >> 2, o = tid & 3;
        float acc2 = 0.f;
        #pragma unroll
        for (int u = 0; u < 16; u++) {
            uint4 uw = *(const uint4*)(smc + OFF_T2 + SWZ((uint32_t)(n * RB + u * 16)));
            uint32_t wv[4] = {uw.x, uw.y, uw.z, uw.w};
            #pragma unroll
            for (int p = 0; p < 4; p++) {
                int m0 = u * 8 + p * 2;
                acc2 += bf_lo(wv[p]) * s_z[m0 * 4 + o] + bf_hi(wv[p]) * s_z[(m0 + 1) * 4 + o];
            }
        }
        s_flat[tid] = fmaxf(acc2 + b2[o], 0.f);
    } else {
        s_flat[tid] = 0.f;
    }
    __syncthreads();

    // r = relu(flat @ Wr1 + br1): Wr1^T f32 [64][512] from L2, 16-wide MLP
    {
        int j = tid & 63, p = tid >> 6;   // p in 0..7, i-range [p*64, p*64+64)
        const float4* wrow = (const float4*)g_wr1t + j * 128 + p * 16;
        float a0 = 0.f, a1 = 0.f;
        #pragma unroll
        for (int u = 0; u < 16; u += 2) {
            float4 w0 = wrow[u];
            float4 w1 = wrow[u + 1];
            int i = p * 64 + u * 4;
            a0 += w0.x * s_flat[i]     + w0.y * s_flat[i + 1]
                + w0.z * s_flat[i + 2] + w0.w * s_flat[i + 3];
            a1 += w1.x * s_flat[i + 4] + w1.y * s_flat[i + 5]
                + w1.z * s_flat[i + 6] + w1.w * s_flat[i + 7];
        }
        s_rp[p * 64 + j] = a0 + a1;
    }
    __syncthreads();
    if (tid < 64) {
        float v = br1[tid];
        #pragma unroll
        for (int p = 0; p < 8; p++) v += s_rp[p * 64 + tid];
        s_r[tid] = fmaxf(v, 0.f);
    }
    __syncthreads();

    // logits = r @ Wr2 + br2 ; log_softmax (2 classes)
    if (tid < 64) {
        float rv = s_r[tid];
        float p0 = rv * Wr2[tid * 2 + 0];
        float p1 = rv * Wr2[tid * 2 + 1];
        #pragma unroll
        for (int m = 16; m >= 1; m >>= 1) {
            p0 += __shfl_xor_sync(0xffffffffu, p0, m);
            p1 += __shfl_xor_sync(0xffffffffu, p1, m);
        }
        if ((tid & 31) == 0) {
            s_red[(tid >> 5) * 2 + 0] = p0;
            s_red[(tid >> 5) * 2 + 1] = p1;
        }
    }
    __syncthreads();
    if (tid == 0) {
        float l0 = s_red[0] + s_red[2] + br2[0];
        float l1 = s_red[1] + s_red[3] + br2[1];
        float mx = fmaxf(l0, l1);
        float lse = mx + logf(expf(l0 - mx) + expf(l1 - mx));
        out[(size_t)b * 2 + 0] = l0 - lse;
        out[(size_t)b * 2 + 1] = l1 - lse;
    }
}

extern "C" void kernel_launch(void* const* d_in, const int* in_sizes, int n_in,
                              void* d_out, int out_size) {
    const float* x   = (const float*)d_in[0];
    const float* sup = (const float*)d_in[1];
    const float* W1  = (const float*)d_in[2];
    const float* b1  = (const float*)d_in[3];
    const float* W2  = (const float*)d_in[4];
    const float* b2  = (const float*)d_in[5];
    const float* Wr1 = (const float*)d_in[6];
    const float* br1 = (const float*)d_in[7];
    const float* Wr2 = (const float*)d_in[8];
    const float* br2 = (const float*)d_in[9];
    float* out = (float*)d_out;

    int B = in_sizes[0] / (NN * FIN);

    prep_w1<<<128, 256>>>(W1);
    prep_wr1<<<128, 256>>>(Wr1);

    cudaFuncSetAttribute(gcn_mma, cudaFuncAttributeMaxDynamicSharedMemorySize, SMEM_BYTES);
    gcn_mma<<<B, NTHR, SMEM_BYTES>>>(x, sup, W1, b1, W2, b2, Wr1, br1, Wr2, br2, out);
}

// round 11
// speedup vs baseline: 1.5875x; 1.5875x over previous
#include <cuda_runtime.h>
#include <cuda_bf16.h>
#include <cstdint>

#define NN   116
#define FIN  116
#define HIDD 256
#define RB   256                        // tile row bytes (128 bf16)
#define TILEB (128 * RB)                // 32768
#define NTHR 512

// swizzle for 256B-pitch tiles: spreads row%8 across banks, keeps 16B units
#define SWZ(o) ((uint32_t)(o) ^ (((uint32_t)(o) >> 4) & 0x70u))

// ---- SMEM byte offsets (per CTA total 113664 -> 2 CTAs/SM) ----
#define OFF_T1    0                        // x tile -> sx tile (tail scratch later)
#define OFF_T2    TILEB                    // sup tile
#define OFF_T3    (2 * TILEB)              // W1 half (re-staged per half)
#define OFF_W2    (3 * TILEB)              // 256*4 f32 = 4096
#define OFF_B1V   (OFF_W2 + 4096)          // 256 f32
#define OFF_Z     (OFF_B1V + 1024)         // 128*4 f32 = 2048
#define OFF_ZP    (OFF_Z + 2048)           // 4*128*4 f32 = 8192 (permanent)
#define SMEM_BYTES (OFF_ZP + 8192)         // 113664

// tail scratch overlaid in T1 (sx dead after GEMM_B)
#define OFF_FLAT  OFF_T1                   // 512 f32 (464 + zero pad)
#define OFF_R     (OFF_FLAT + 2048)        // 64 f32
#define OFF_RED   (OFF_R + 256)            // 16 f32

// pre-rounded, pre-swizzled W1 tile images: [half][128 rows k=f][128 cols h'] bf16
__device__ unsigned char g_w1[2 * TILEB];
// pre-transposed Wr1^T: [64 rows j][512 cols i] f32 (i >= 464 zero)
__device__ float g_wr1t[64 * 512];

__device__ __forceinline__ uint32_t smem_u32(const void* p) {
    uint32_t a;
    asm("{ .reg .u64 t; cvta.to.shared.u64 t, %1; cvt.u32.u64 %0, t; }" : "=r"(a) : "l"(p));
    return a;
}
__device__ __forceinline__ uint32_t pack_bf16(float a, float b) {
    __nv_bfloat162 v = __float22bfloat162_rn(make_float2(a, b));
    return *(uint32_t*)&v;
}
__device__ __forceinline__ float bf_lo(uint32_t w) {
    return __bfloat162float(__ushort_as_bfloat16((unsigned short)(w & 0xffff)));
}
__device__ __forceinline__ float bf_hi(uint32_t w) {
    return __bfloat162float(__ushort_as_bfloat16((unsigned short)(w >> 16)));
}

__device__ __forceinline__ void cpasync16(uint32_t s, const void* g) {
    asm volatile("cp.async.cg.shared.global [%0], [%1], 16;" :: "r"(s), "l"(g));
}
#define CP_COMMIT() asm volatile("cp.async.commit_group;")
#define CP_WAIT0()  asm volatile("cp.async.wait_group 0;")

#define LDSM_X4(r0, r1, r2, r3, addr) \
    asm volatile("ldmatrix.sync.aligned.m8n8.x4.shared.b16 {%0,%1,%2,%3}, [%4];" \
        : "=r"(r0), "=r"(r1), "=r"(r2), "=r"(r3) : "r"(addr))
#define LDSM_X4T(r0, r1, r2, r3, addr) \
    asm volatile("ldmatrix.sync.aligned.m8n8.x4.trans.shared.b16 {%0,%1,%2,%3}, [%4];" \
        : "=r"(r0), "=r"(r1), "=r"(r2), "=r"(r3) : "r"(addr))

__device__ __forceinline__ void mma16816(float* d, uint32_t a0, uint32_t a1,
                                         uint32_t a2, uint32_t a3,
                                         uint32_t b0, uint32_t b1) {
    asm volatile(
        "mma.sync.aligned.m16n8k16.row.col.f32.bf16.bf16.f32 "
        "{%0,%1,%2,%3}, {%4,%5,%6,%7}, {%8,%9}, {%0,%1,%2,%3};"
        : "+f"(d[0]), "+f"(d[1]), "+f"(d[2]), "+f"(d[3])
        : "r"(a0), "r"(a1), "r"(a2), "r"(a3), "r"(b0), "r"(b1));
}

// GEMM, warp tile 32x32, B stored K-major [k][n]: trans LDSM for B
__device__ __forceinline__ void mma32(float acc[2][4][4],
                                      uint32_t aTile, uint32_t bTile,
                                      int r0, int c0, int lane) {
    const int row_in = (lane & 7) | (((lane >> 3) & 1) << 3);
    const int col_in = (lane >> 4) << 3;
    const uint32_t aRel0 = (uint32_t)((r0 + row_in) * RB + col_in * 2);
    const uint32_t aRel1 = aRel0 + 16 * RB;
    const uint32_t mA0 = (aRel0 >> 4) & 0x70u;
    const uint32_t mA1 = (aRel1 >> 4) & 0x70u;
    const uint32_t bRel0 = (uint32_t)(row_in * RB + (c0 + col_in) * 2);
    const uint32_t bRel1 = bRel0 + 32;
    uint32_t b0 = bTile + SWZ(bRel0);
    uint32_t b1 = bTile + SWZ(bRel1);
    #pragma unroll
    for (int k = 0; k < 8; ++k) {
        const uint32_t ca = (uint32_t)(k * 32);
        uint32_t a0, a1, a2, a3, a4, a5, a6, a7;
        LDSM_X4(a0, a1, a2, a3, aTile + ((aRel0 + ca) ^ mA0));
        LDSM_X4(a4, a5, a6, a7, aTile + ((aRel1 + ca) ^ mA1));
        uint32_t p0, p1, p2, p3, q0, q1, q2, q3;
        LDSM_X4T(p0, p1, p2, p3, b0);
        LDSM_X4T(q0, q1, q2, q3, b1);
        mma16816(acc[0][0], a0, a1, a2, a3, p0, p1);
        mma16816(acc[0][1], a0, a1, a2, a3, p2, p3);
        mma16816(acc[0][2], a0, a1, a2, a3, q0, q1);
        mma16816(acc[0][3], a0, a1, a2, a3, q2, q3);
        mma16816(acc[1][0], a4, a5, a6, a7, p0, p1);
        mma16816(acc[1][1], a4, a5, a6, a7, p2, p3);
        mma16816(acc[1][2], a4, a5, a6, a7, q0, q1);
        mma16816(acc[1][3], a4, a5, a6, a7, q2, q3);
        b0 += 16 * RB;      // +16 k-rows (mask bits invariant)
        b1 += 16 * RB;
    }
}

// ---- prep: round W1 into pre-swizzled global bf16 tile images (idempotent) ----
__global__ void prep_w1(const float* __restrict__ W1) {
    int idx = blockIdx.x * blockDim.x + threadIdx.x;
    if (idx >= 2 * 128 * 128) return;
    int half = idx >> 14;
    int rem  = idx & 16383;
    int r = rem >> 7, c = rem & 127;          // r = f (K), c = h' (N)
    float v = (r < FIN) ? W1[r * HIDD + half * 128 + c] : 0.f;
    uint32_t off = SWZ((uint32_t)(r * RB + c * 2));
    *(__nv_bfloat16*)(g_w1 + half * TILEB + off) = __float2bfloat16_rn(v);
}

// ---- prep: Wr1^T [j][i] f32, i padded to 512 with zeros (idempotent) ----
__global__ void prep_wr1(const float* __restrict__ Wr1) {
    int idx = blockIdx.x * blockDim.x + threadIdx.x;
    if (idx >= 64 * 512) return;
    int j = idx >> 9, i = idx & 511;
    g_wr1t[idx] = (i < 464) ? Wr1[(size_t)i * 64 + j] : 0.f;
}

extern __shared__ char smc[];

__global__ void __launch_bounds__(NTHR, 2) gcn_mma(
    const float* __restrict__ x,   const float* __restrict__ sup,
    const float* __restrict__ W1,  const float* __restrict__ b1,
    const float* __restrict__ W2,  const float* __restrict__ b2,
    const float* __restrict__ Wr1, const float* __restrict__ br1,
    const float* __restrict__ Wr2, const float* __restrict__ br2,
    float* __restrict__ out)
{
    const int tid  = threadIdx.x;
    const int b    = blockIdx.x;
    const int lane = tid & 31;
    const int warp = tid >> 5;            // 0..15
    const int r0   = (warp >> 2) * 32;    // 4 row blocks
    const int c0   = (warp & 3) * 32;     // 4 col blocks
    const int wc   = warp & 3;

    float* s_w2   = (float*)(smc + OFF_W2);
    float* s_b1   = (float*)(smc + OFF_B1V);
    float* s_z    = (float*)(smc + OFF_Z);
    float* s_zp   = (float*)(smc + OFF_ZP);
    float* s_flat = (float*)(smc + OFF_FLAT);
    float* s_r    = (float*)(smc + OFF_R);
    float* s_red  = (float*)(smc + OFF_RED);

    const uint32_t su = smem_u32(smc);

    // prefetch W1 half0 into T3 via cp.async — hidden behind convert + GEMM_A
    for (int i = tid; i < TILEB / 16; i += NTHR)
        cpasync16(su + OFF_T3 + i * 16, g_w1 + i * 16);
    CP_COMMIT();

    // zero ONLY the pad regions of x/sup tiles:
    //  (a) full rows 116..127 (linear store OK: SWZ permutes within a row)
    const uint4 z4 = make_uint4(0, 0, 0, 0);
    for (int i = tid; i < 12 * 16 * 2; i += NTHR) {
        int t   = i / (12 * 16);
        int rem = i % (12 * 16);
        int m = 116 + (rem >> 4), u = rem & 15;
        *(uint4*)(smc + (t ? OFF_T2 : OFF_T1) + (uint32_t)(m * RB + u * 16)) = z4;
    }
    //  (b) cols 112..127 of rows 0..115 (2 swizzled 16B units; converter
    //      overwrites bytes 224..231 after the barrier)
    for (int i = tid; i < 116 * 2 * 2; i += NTHR) {
        int t   = i & 1;
        int rem = i >> 1;
        int m = rem >> 1, u = rem & 1;
        uint32_t off = SWZ((uint32_t)(m * RB + 224 + u * 16));
        *(uint4*)(smc + (t ? OFF_T2 : OFF_T1) + off) = z4;
    }
    for (int i = tid; i < 2048; i += NTHR) s_zp[i] = 0.f;
    for (int i = tid; i < HIDD * 4; i += NTHR) s_w2[i] = W2[i];
    for (int i = tid; i < HIDD; i += NTHR)     s_b1[i] = b1[i];
    __syncthreads();

    // load + convert x[b], sup[b] -> bf16 swizzled tiles [m][k]
    const float* xb = x   + (size_t)b * NN * FIN;
    const float* sb = sup + (size_t)b * NN * NN;
    for (int q = tid; q < NN * 29; q += NTHR) {
        int m = q / 29, c4 = (q % 29) * 4;
        uint32_t off = SWZ((uint32_t)(m * RB + c4 * 2));
        float4 vx = *(const float4*)(xb + m * FIN + c4);
        uint2 w;
        w.x = pack_bf16(vx.x, vx.y);
        w.y = pack_bf16(vx.z, vx.w);
        *(uint2*)(smc + OFF_T1 + off) = w;
        float4 vs = *(const float4*)(sb + m * NN + c4);
        w.x = pack_bf16(vs.x, vs.y);
        w.y = pack_bf16(vs.z, vs.w);
        *(uint2*)(smc + OFF_T2 + off) = w;
    }
    __syncthreads();

    // ---- GEMM_A: sx = sup @ x  (A = T2, B = T1 K-major, trans LDSM) ----
    {
        float acc[2][4][4];
        #pragma unroll
        for (int i = 0; i < 2; i++)
            #pragma unroll
            for (int j = 0; j < 4; j++)
                #pragma unroll
                for (int d = 0; d < 4; d++) acc[i][j][d] = 0.f;

        mma32(acc, su + OFF_T2, su + OFF_T1, r0, c0, lane);
        __syncthreads();   // all x reads done before overwrite

        // store sx as bf16 into T1 ([n][f] layout = A of GEMM_B)
        int grow = lane >> 2, gcol = (lane & 3) * 2;
        #pragma unroll
        for (int i = 0; i < 2; i++) {
            #pragma unroll
            for (int j = 0; j < 4; j++) {
                int rr = r0 + i * 16 + grow;
                int cc = c0 + j * 8 + gcol;
                *(uint32_t*)(smc + OFF_T1 + SWZ((uint32_t)(rr * RB + cc * 2))) =
                    pack_bf16(acc[i][j][0], acc[i][j][1]);
                *(uint32_t*)(smc + OFF_T1 + SWZ((uint32_t)((rr + 8) * RB + cc * 2))) =
                    pack_bf16(acc[i][j][2], acc[i][j][3]);
            }
        }
    }
    CP_WAIT0();      // W1 half0 landed
    __syncthreads();

    for (int half = 0; half < 2; ++half) {
        // ---- GEMM_B: h1_half = sx @ W1half (A = T1, B = T3 K-major, trans) ----
        float acc[2][4][4];
        #pragma unroll
        for (int i = 0; i < 2; i++)
            #pragma unroll
            for (int j = 0; j < 4; j++)
                #pragma unroll
                for (int d = 0; d < 4; d++) acc[i][j][d] = 0.f;

        mma32(acc, su + OFF_T1, su + OFF_T3, r0, c0, lane);

        // restage W1 half1 NOW (T3 reads done after barrier); overlaps epilogue
        if (half == 0) {
            __syncthreads();   // all warps' T3 reads done
            for (int i = tid; i < TILEB / 16; i += NTHR)
                cpasync16(su + OFF_T3 + i * 16, g_w1 + TILEB + i * 16);
            CP_COMMIT();
        }

        // epilogue: relu(h1 + b1) contracted with W2 -> zacc -> s_zp
        {
            float zacc[4][4];
            #pragma unroll
            for (int s = 0; s < 4; s++)
                #pragma unroll
                for (int o = 0; o < 4; o++) zacc[s][o] = 0.f;
            int gcol = (lane & 3) * 2;
            #pragma unroll
            for (int i = 0; i < 2; i++) {
                #pragma unroll
                for (int j = 0; j < 4; j++) {
                    int h = half * 128 + c0 + j * 8 + gcol;
                    float b1a = s_b1[h], b1b = s_b1[h + 1];
                    float4 wa = *(const float4*)&s_w2[h * 4];
                    float4 wb = *(const float4*)&s_w2[(h + 1) * 4];
                    float v0 = fmaxf(acc[i][j][0] + b1a, 0.f);
                    float v1 = fmaxf(acc[i][j][1] + b1b, 0.f);
                    float v2 = fmaxf(acc[i][j][2] + b1a, 0.f);
                    float v3 = fmaxf(acc[i][j][3] + b1b, 0.f);
                    zacc[i*2+0][0] += v0 * wa.x + v1 * wb.x;
                    zacc[i*2+0][1] += v0 * wa.y + v1 * wb.y;
                    zacc[i*2+0][2] += v0 * wa.z + v1 * wb.z;
                    zacc[i*2+0][3] += v0 * wa.w + v1 * wb.w;
                    zacc[i*2+1][0] += v2 * wa.x + v3 * wb.x;
                    zacc[i*2+1][1] += v2 * wa.y + v3 * wb.y;
                    zacc[i*2+1][2] += v2 * wa.z + v3 * wb.z;
                    zacc[i*2+1][3] += v2 * wa.w + v3 * wb.w;
                }
            }
            // reduce over the 4 lanes sharing the same rows, accumulate to zp
            #pragma unroll
            for (int s = 0; s < 4; s++) {
                #pragma unroll
                for (int o = 0; o < 4; o++) {
                    float v = zacc[s][o];
                    v += __shfl_xor_sync(0xffffffffu, v, 1);
                    v += __shfl_xor_sync(0xffffffffu, v, 2);
                    zacc[s][o] = v;
                }
            }
            if ((lane & 3) == 0) {
                #pragma unroll
                for (int s = 0; s < 4; s++) {
                    int rr = r0 + (s >> 1) * 16 + (lane >> 2) + (s & 1) * 8;
                    #pragma unroll
                    for (int o = 0; o < 4; o++)
                        s_zp[(wc * 128 + rr) * 4 + o] += zacc[s][o];
                }
            }
        }

        if (half == 0) {
            CP_WAIT0();      // W1 half1 landed (copy overlapped the epilogue)
            __syncthreads();
        }
    }
    __syncthreads();   // GEMMs done; T1 becomes tail scratch

    // z[n][o] = sum over the 4 column-group partials
    {
        int n = tid >> 2, o = tid & 3;   // exactly 512 items
        s_z[n * 4 + o] = s_zp[(0 * 128 + n) * 4 + o] + s_zp[(1 * 128 + n) * 4 + o]
                       + s_zp[(2 * 128 + n) * 4 + o] + s_zp[(3 * 128 + n) * 4 + o];
    }
    __syncthreads();

    // h2 = relu(sup @ z + b2) -> flat[464], pad to 512 with zeros
    if (tid < NN * 4) {
        int n = tid >> 2, o = tid & 3;
        float acc2 = 0.f;
        #pragma unroll
        for (int u = 0; u < 16; u++) {
            uint4 uw = *(const uint4*)(smc + OFF_T2 + SWZ((uint32_t)(n * RB + u * 16)));
            uint32_t wv[4] = {uw.x, uw.y, uw.z, uw.w};
            #pragma unroll
            for (int p = 0; p < 4; p++) {
                int m0 = u * 8 + p * 2;
                acc2 += bf_lo(wv[p]) * s_z[m0 * 4 + o] + bf_hi(wv[p]) * s_z[(m0 + 1) * 4 + o];
            }
        }
        s_flat[tid] = fmaxf(acc2 + b2[o], 0.f);
    } else {
        s_flat[tid] = 0.f;
    }
    __syncthreads();

    // r = relu(flat @ Wr1 + br1): warp w handles j = w*4..w*4+3; 32 lanes read
    // one 2KB row of Wr1^T coalesced (float4) and shfl-reduce.
    {
        const float4* fl4 = (const float4*)s_flat;   // 128 float4
        #pragma unroll
        for (int jj = 0; jj < 4; ++jj) {
            int j = warp * 4 + jj;
            const float4* wrow = (const float4*)(g_wr1t + (size_t)j * 512);
            float a = 0.f;
            #pragma unroll
            for (int u = 0; u < 4; ++u) {
                float4 w4 = wrow[lane + u * 32];
                float4 f4 = fl4[lane + u * 32];
                a += w4.x * f4.x + w4.y * f4.y + w4.z * f4.z + w4.w * f4.w;
            }
            a += __shfl_xor_sync(0xffffffffu, a, 16);
            a += __shfl_xor_sync(0xffffffffu, a, 8);
            a += __shfl_xor_sync(0xffffffffu, a, 4);
            a += __shfl_xor_sync(0xffffffffu, a, 2);
            a += __shfl_xor_sync(0xffffffffu, a, 1);
            if (lane == 0) s_r[j] = fmaxf(a + br1[j], 0.f);
        }
    }
    __syncthreads();

    // logits = r @ Wr2 + br2 ; log_softmax (2 classes)
    if (tid < 64) {
        float rv = s_r[tid];
        float p0 = rv * Wr2[tid * 2 + 0];
        float p1 = rv * Wr2[tid * 2 + 1];
        #pragma unroll
        for (int m = 16; m >= 1; m >>= 1) {
            p0 += __shfl_xor_sync(0xffffffffu, p0, m);
            p1 += __shfl_xor_sync(0xffffffffu, p1, m);
        }
        if ((tid & 31) == 0) {
            s_red[(tid >> 5) * 2 + 0] = p0;
            s_red[(tid >> 5) * 2 + 1] = p1;
        }
    }
    __syncthreads();
    if (tid == 0) {
        float l0 = s_red[0] + s_red[2] + br2[0];
        float l1 = s_red[1] + s_red[3] + br2[1];
        float mx = fmaxf(l0, l1);
        float lse = mx + logf(expf(l0 - mx) + expf(l1 - mx));
        out[(size_t)b * 2 + 0] = l0 - lse;
        out[(size_t)b * 2 + 1] = l1 - lse;
    }
}

extern "C" void kernel_launch(void* const* d_in, const int* in_sizes, int n_in,
                              void* d_out, int out_size) {
    const float* x   = (const float*)d_in[0];
    const float* sup = (const float*)d_in[1];
    const float* W1  = (const float*)d_in[2];
    const float* b1  = (const float*)d_in[3];
    const float* W2  = (const float*)d_in[4];
    const float* b2  = (const float*)d_in[5];
    const float* Wr1 = (const float*)d_in[6];
    const float* br1 = (const float*)d_in[7];
    const float* Wr2 = (const float*)d_in[8];
    const float* br2 = (const float*)d_in[9];
    float* out = (float*)d_out;

    int B = in_sizes[0] / (NN * FIN);

    prep_w1<<<128, 256>>>(W1);
    prep_wr1<<<128, 256>>>(Wr1);

    cudaFuncSetAttribute(gcn_mma, cudaFuncAttributeMaxDynamicSharedMemorySize, SMEM_BYTES);
    gcn_mma<<<B, NTHR, SMEM_BYTES>>>(x, sup, W1, b1, W2, b2, Wr1, br1, Wr2, br2, out);
}

// round 12
// speedup vs baseline: 1.7189x; 1.0828x over previous
#include <cuda_runtime.h>
#include <cuda_bf16.h>
#include <cstdint>

#define NN   116
#define FIN  116
#define HIDD 256
#define RB   256                        // tile row bytes (128 bf16)
#define TILEB (128 * RB)                // 32768
#define NTHR 512

// swizzle for 256B-pitch tiles: spreads row%8 across banks, keeps 16B units
#define SWZ(o) ((uint32_t)(o) ^ (((uint32_t)(o) >> 4) & 0x70u))

// ---- SMEM byte offsets (per CTA total 82944 -> 2 CTAs/SM, ~62KB L1D left) ----
#define OFF_T1    0                        // x tile -> sx tile (tail scratch later)
#define OFF_T2    TILEB                    // sup tile
#define OFF_W2    (2 * TILEB)              // 256*4 f32 = 4096
#define OFF_B1V   (OFF_W2 + 4096)          // 256 f32
#define OFF_Z     (OFF_B1V + 1024)         // 128*4 f32 = 2048
#define OFF_ZP    (OFF_Z + 2048)           // 4*128*4 f32 = 8192
#define SMEM_BYTES (OFF_ZP + 8192)         // 82944

// tail scratch overlaid in T1 (sx dead after GEMM_B)
#define OFF_FLAT  OFF_T1                   // 512 f32 (464 + zero pad)
#define OFF_R     (OFF_FLAT + 2048)        // 64 f32
#define OFF_RED   (OFF_R + 256)            // 16 f32

// W1 fragment image: uint32 regs, index = ((((half*4+wc)*8+ks)*2+grp)*32+lane)*4+u
// reg r = grp*4+u; value = pack_bf16(W1[k][h], W1[k+1][h]),
//   k = ks*16 + (r&1)*8 + (lane%4)*2,  h = half*128 + wc*32 + (r>>1)*8 + lane/4
__device__ uint32_t g_w1frag[16384];       // 64KB
// pre-transposed Wr1^T: [64 rows j][512 cols i] f32 (i >= 464 zero)
__device__ float g_wr1t[64 * 512];

__device__ __forceinline__ uint32_t smem_u32(const void* p) {
    uint32_t a;
    asm("{ .reg .u64 t; cvta.to.shared.u64 t, %1; cvt.u32.u64 %0, t; }" : "=r"(a) : "l"(p));
    return a;
}
__device__ __forceinline__ uint32_t pack_bf16(float a, float b) {
    __nv_bfloat162 v = __float22bfloat162_rn(make_float2(a, b));
    return *(uint32_t*)&v;
}
__device__ __forceinline__ float bf_lo(uint32_t w) {
    return __bfloat162float(__ushort_as_bfloat16((unsigned short)(w & 0xffff)));
}
__device__ __forceinline__ float bf_hi(uint32_t w) {
    return __bfloat162float(__ushort_as_bfloat16((unsigned short)(w >> 16)));
}

#define LDSM_X4(r0, r1, r2, r3, addr) \
    asm volatile("ldmatrix.sync.aligned.m8n8.x4.shared.b16 {%0,%1,%2,%3}, [%4];" \
        : "=r"(r0), "=r"(r1), "=r"(r2), "=r"(r3) : "r"(addr))
#define LDSM_X4T(r0, r1, r2, r3, addr) \
    asm volatile("ldmatrix.sync.aligned.m8n8.x4.trans.shared.b16 {%0,%1,%2,%3}, [%4];" \
        : "=r"(r0), "=r"(r1), "=r"(r2), "=r"(r3) : "r"(addr))

__device__ __forceinline__ void mma16816(float* d, uint32_t a0, uint32_t a1,
                                         uint32_t a2, uint32_t a3,
                                         uint32_t b0, uint32_t b1) {
    asm volatile(
        "mma.sync.aligned.m16n8k16.row.col.f32.bf16.bf16.f32 "
        "{%0,%1,%2,%3}, {%4,%5,%6,%7}, {%8,%9}, {%0,%1,%2,%3};"
        : "+f"(d[0]), "+f"(d[1]), "+f"(d[2]), "+f"(d[3])
        : "r"(a0), "r"(a1), "r"(a2), "r"(a3), "r"(b0), "r"(b1));
}

// GEMM, warp tile 32x32, B from SMEM K-major [k][n] via trans LDSM (GEMM_A)
__device__ __forceinline__ void mma32(float acc[2][4][4],
                                      uint32_t aTile, uint32_t bTile,
                                      int r0, int c0, int lane) {
    const int row_in = (lane & 7) | (((lane >> 3) & 1) << 3);
    const int col_in = (lane >> 4) << 3;
    const uint32_t aRel0 = (uint32_t)((r0 + row_in) * RB + col_in * 2);
    const uint32_t aRel1 = aRel0 + 16 * RB;
    const uint32_t mA0 = (aRel0 >> 4) & 0x70u;
    const uint32_t mA1 = (aRel1 >> 4) & 0x70u;
    const uint32_t bRel0 = (uint32_t)(row_in * RB + (c0 + col_in) * 2);
    const uint32_t bRel1 = bRel0 + 32;
    uint32_t b0 = bTile + SWZ(bRel0);
    uint32_t b1 = bTile + SWZ(bRel1);
    #pragma unroll
    for (int k = 0; k < 8; ++k) {
        const uint32_t ca = (uint32_t)(k * 32);
        uint32_t a0, a1, a2, a3, a4, a5, a6, a7;
        LDSM_X4(a0, a1, a2, a3, aTile + ((aRel0 + ca) ^ mA0));
        LDSM_X4(a4, a5, a6, a7, aTile + ((aRel1 + ca) ^ mA1));
        uint32_t p0, p1, p2, p3, q0, q1, q2, q3;
        LDSM_X4T(p0, p1, p2, p3, b0);
        LDSM_X4T(q0, q1, q2, q3, b1);
        mma16816(acc[0][0], a0, a1, a2, a3, p0, p1);
        mma16816(acc[0][1], a0, a1, a2, a3, p2, p3);
        mma16816(acc[0][2], a0, a1, a2, a3, q0, q1);
        mma16816(acc[0][3], a0, a1, a2, a3, q2, q3);
        mma16816(acc[1][0], a4, a5, a6, a7, p0, p1);
        mma16816(acc[1][1], a4, a5, a6, a7, p2, p3);
        mma16816(acc[1][2], a4, a5, a6, a7, q0, q1);
        mma16816(acc[1][3], a4, a5, a6, a7, q2, q3);
        b0 += 16 * RB;      // +16 k-rows (mask bits invariant)
        b1 += 16 * RB;
    }
}

// GEMM, warp tile 32x32, B fragments streamed from global image via LDG.128
__device__ __forceinline__ void mma32_gB(float acc[2][4][4],
                                         uint32_t aTile, const uint4* wfrag,
                                         int r0, int lane) {
    const int row_in = (lane & 7) | (((lane >> 3) & 1) << 3);
    const int col_in = (lane >> 4) << 3;
    const uint32_t aRel0 = (uint32_t)((r0 + row_in) * RB + col_in * 2);
    const uint32_t aRel1 = aRel0 + 16 * RB;
    const uint32_t mA0 = (aRel0 >> 4) & 0x70u;
    const uint32_t mA1 = (aRel1 >> 4) & 0x70u;
    #pragma unroll
    for (int k = 0; k < 8; ++k) {
        const uint32_t ca = (uint32_t)(k * 32);
        uint32_t a0, a1, a2, a3, a4, a5, a6, a7;
        LDSM_X4(a0, a1, a2, a3, aTile + ((aRel0 + ca) ^ mA0));
        LDSM_X4(a4, a5, a6, a7, aTile + ((aRel1 + ca) ^ mA1));
        uint4 g0 = wfrag[k * 64 + lane];        // regs p0..p3 (coalesced 512B)
        uint4 g1 = wfrag[k * 64 + 32 + lane];   // regs q0..q3
        mma16816(acc[0][0], a0, a1, a2, a3, g0.x, g0.y);
        mma16816(acc[0][1], a0, a1, a2, a3, g0.z, g0.w);
        mma16816(acc[0][2], a0, a1, a2, a3, g1.x, g1.y);
        mma16816(acc[0][3], a0, a1, a2, a3, g1.z, g1.w);
        mma16816(acc[1][0], a4, a5, a6, a7, g0.x, g0.y);
        mma16816(acc[1][1], a4, a5, a6, a7, g0.z, g0.w);
        mma16816(acc[1][2], a4, a5, a6, a7, g1.x, g1.y);
        mma16816(acc[1][3], a4, a5, a6, a7, g1.z, g1.w);
    }
}

// ---- fused prep: W1 fragment image + Wr1^T (idempotent) ----
__global__ void prep_weights(const float* __restrict__ W1,
                             const float* __restrict__ Wr1) {
    int idx = blockIdx.x * blockDim.x + threadIdx.x;
    if (idx < 16384) {
        // decode: u(2) lane(5) grp(1) ks(3) wc(2) half(1)
        int u    = idx & 3;
        int lane = (idx >> 2) & 31;
        int grp  = (idx >> 7) & 1;
        int ks   = (idx >> 8) & 7;
        int wc   = (idx >> 11) & 3;
        int half = idx >> 13;
        int r = grp * 4 + u;
        int k = ks * 16 + (r & 1) * 8 + (lane & 3) * 2;
        int h = half * 128 + wc * 32 + (r >> 1) * 8 + (lane >> 2);
        float v0 = (k     < FIN) ? W1[(size_t)k * HIDD + h]       : 0.f;
        float v1 = (k + 1 < FIN) ? W1[(size_t)(k + 1) * HIDD + h] : 0.f;
        g_w1frag[idx] = pack_bf16(v0, v1);
    } else if (idx < 16384 + 64 * 512) {
        int q = idx - 16384;
        int j = q >> 9, i = q & 511;
        g_wr1t[q] = (i < 464) ? Wr1[(size_t)i * 64 + j] : 0.f;
    }
}

extern __shared__ char smc[];

__global__ void __launch_bounds__(NTHR, 2) gcn_mma(
    const float* __restrict__ x,   const float* __restrict__ sup,
    const float* __restrict__ W1,  const float* __restrict__ b1,
    const float* __restrict__ W2,  const float* __restrict__ b2,
    const float* __restrict__ Wr1, const float* __restrict__ br1,
    const float* __restrict__ Wr2, const float* __restrict__ br2,
    float* __restrict__ out)
{
    const int tid  = threadIdx.x;
    const int b    = blockIdx.x;
    const int lane = tid & 31;
    const int warp = tid >> 5;            // 0..15
    const int r0   = (warp >> 2) * 32;    // 4 row blocks
    const int c0   = (warp & 3) * 32;     // 4 col blocks
    const int wc   = warp & 3;

    float* s_w2   = (float*)(smc + OFF_W2);
    float* s_b1   = (float*)(smc + OFF_B1V);
    float* s_z    = (float*)(smc + OFF_Z);
    float* s_zp   = (float*)(smc + OFF_ZP);
    float* s_flat = (float*)(smc + OFF_FLAT);
    float* s_r    = (float*)(smc + OFF_R);
    float* s_red  = (float*)(smc + OFF_RED);

    const uint32_t su = smem_u32(smc);

    // zero ONLY the pad regions of x/sup tiles:
    //  (a) full rows 116..127
    const uint4 z4 = make_uint4(0, 0, 0, 0);
    for (int i = tid; i < 12 * 16 * 2; i += NTHR) {
        int t   = i / (12 * 16);
        int rem = i % (12 * 16);
        int m = 116 + (rem >> 4), u = rem & 15;
        *(uint4*)(smc + (t ? OFF_T2 : OFF_T1) + (uint32_t)(m * RB + u * 16)) = z4;
    }
    //  (b) cols 112..127 of rows 0..115 (2 swizzled 16B units; converter
    //      overwrites bytes 224..231 after the barrier)
    for (int i = tid; i < 116 * 2 * 2; i += NTHR) {
        int t   = i & 1;
        int rem = i >> 1;
        int m = rem >> 1, u = rem & 1;
        uint32_t off = SWZ((uint32_t)(m * RB + 224 + u * 16));
        *(uint4*)(smc + (t ? OFF_T2 : OFF_T1) + off) = z4;
    }
    for (int i = tid; i < HIDD * 4; i += NTHR) s_w2[i] = W2[i];
    for (int i = tid; i < HIDD; i += NTHR)     s_b1[i] = b1[i];
    __syncthreads();

    // load + convert x[b], sup[b] -> bf16 swizzled tiles [m][k]
    const float* xb = x   + (size_t)b * NN * FIN;
    const float* sb = sup + (size_t)b * NN * NN;
    for (int q = tid; q < NN * 29; q += NTHR) {
        int m = q / 29, c4 = (q % 29) * 4;
        uint32_t off = SWZ((uint32_t)(m * RB + c4 * 2));
        float4 vx = *(const float4*)(xb + m * FIN + c4);
        uint2 w;
        w.x = pack_bf16(vx.x, vx.y);
        w.y = pack_bf16(vx.z, vx.w);
        *(uint2*)(smc + OFF_T1 + off) = w;
        float4 vs = *(const float4*)(sb + m * NN + c4);
        w.x = pack_bf16(vs.x, vs.y);
        w.y = pack_bf16(vs.z, vs.w);
        *(uint2*)(smc + OFF_T2 + off) = w;
    }
    __syncthreads();

    // ---- GEMM_A: sx = sup @ x  (A = T2, B = T1 K-major, trans LDSM) ----
    {
        float acc[2][4][4];
        #pragma unroll
        for (int i = 0; i < 2; i++)
            #pragma unroll
            for (int j = 0; j < 4; j++)
                #pragma unroll
                for (int d = 0; d < 4; d++) acc[i][j][d] = 0.f;

        mma32(acc, su + OFF_T2, su + OFF_T1, r0, c0, lane);
        __syncthreads();   // all x reads done before overwrite

        // store sx as bf16 into T1 ([n][f] layout = A of GEMM_B)
        int grow = lane >> 2, gcol = (lane & 3) * 2;
        #pragma unroll
        for (int i = 0; i < 2; i++) {
            #pragma unroll
            for (int j = 0; j < 4; j++) {
                int rr = r0 + i * 16 + grow;
                int cc = c0 + j * 8 + gcol;
                *(uint32_t*)(smc + OFF_T1 + SWZ((uint32_t)(rr * RB + cc * 2))) =
                    pack_bf16(acc[i][j][0], acc[i][j][1]);
                *(uint32_t*)(smc + OFF_T1 + SWZ((uint32_t)((rr + 8) * RB + cc * 2))) =
                    pack_bf16(acc[i][j][2], acc[i][j][3]);
            }
        }
    }
    __syncthreads();

    // ---- GEMM_B both halves, no syncs: h1 = sx @ W1 (B frags from global) ----
    #pragma unroll
    for (int half = 0; half < 2; ++half) {
        float acc[2][4][4];
        #pragma unroll
        for (int i = 0; i < 2; i++)
            #pragma unroll
            for (int j = 0; j < 4; j++)
                #pragma unroll
                for (int d = 0; d < 4; d++) acc[i][j][d] = 0.f;

        const uint4* wfrag = (const uint4*)g_w1frag + (size_t)(half * 4 + wc) * 512;
        mma32_gB(acc, su + OFF_T1, wfrag, r0, lane);

        // epilogue: relu(h1 + b1) contracted with W2 -> zacc -> s_zp
        float zacc[4][4];
        #pragma unroll
        for (int s = 0; s < 4; s++)
            #pragma unroll
            for (int o = 0; o < 4; o++) zacc[s][o] = 0.f;
        {
            int gcol = (lane & 3) * 2;
            #pragma unroll
            for (int i = 0; i < 2; i++) {
                #pragma unroll
                for (int j = 0; j < 4; j++) {
                    int h = half * 128 + c0 + j * 8 + gcol;
                    float b1a = s_b1[h], b1b = s_b1[h + 1];
                    float4 wa = *(const float4*)&s_w2[h * 4];
                    float4 wb = *(const float4*)&s_w2[(h + 1) * 4];
                    float v0 = fmaxf(acc[i][j][0] + b1a, 0.f);
                    float v1 = fmaxf(acc[i][j][1] + b1b, 0.f);
                    float v2 = fmaxf(acc[i][j][2] + b1a, 0.f);
                    float v3 = fmaxf(acc[i][j][3] + b1b, 0.f);
                    zacc[i*2+0][0] += v0 * wa.x + v1 * wb.x;
                    zacc[i*2+0][1] += v0 * wa.y + v1 * wb.y;
                    zacc[i*2+0][2] += v0 * wa.z + v1 * wb.z;
                    zacc[i*2+0][3] += v0 * wa.w + v1 * wb.w;
                    zacc[i*2+1][0] += v2 * wa.x + v3 * wb.x;
                    zacc[i*2+1][1] += v2 * wa.y + v3 * wb.y;
                    zacc[i*2+1][2] += v2 * wa.z + v3 * wb.z;
                    zacc[i*2+1][3] += v2 * wa.w + v3 * wb.w;
                }
            }
        }
        // reduce over the 4 lanes sharing the same rows; half0 assigns, half1 adds
        #pragma unroll
        for (int s = 0; s < 4; s++) {
            #pragma unroll
            for (int o = 0; o < 4; o++) {
                float v = zacc[s][o];
                v += __shfl_xor_sync(0xffffffffu, v, 1);
                v += __shfl_xor_sync(0xffffffffu, v, 2);
                zacc[s][o] = v;
            }
        }
        if ((lane & 3) == 0) {
            #pragma unroll
            for (int s = 0; s < 4; s++) {
                int rr = r0 + (s >> 1) * 16 + (lane >> 2) + (s & 1) * 8;
                #pragma unroll
                for (int o = 0; o < 4; o++) {
                    float* dst = &s_zp[(wc * 128 + rr) * 4 + o];
                    if (half == 0) *dst = zacc[s][o];
                    else           *dst += zacc[s][o];
                }
            }
        }
    }
    __syncthreads();   // GEMMs done; T1 becomes tail scratch

    // z[n][o] = sum over the 4 column-group partials
    {
        int n = tid >> 2, o = tid & 3;   // exactly 512 items
        s_z[n * 4 + o] = s_zp[(0 * 128 + n) * 4 + o] + s_zp[(1 * 128 + n) * 4 + o]
                       + s_zp[(2 * 128 + n) * 4 + o] + s_zp[(3 * 128 + n) * 4 + o];
    }
    __syncthreads();

    // h2 = relu(sup @ z + b2) -> flat[464], pad to 512 with zeros
    if (tid < NN * 4) {
        int n = tid >> 2, o = tid & 3;
        float acc2 = 0.f;
        #pragma unroll
        for (int u = 0; u < 16; u++) {
            uint4 uw = *(const uint4*)(smc + OFF_T2 + SWZ((uint32_t)(n * RB + u * 16)));
            uint32_t wv[4] = {uw.x, uw.y, uw.z, uw.w};
            #pragma unroll
            for (int p = 0; p < 4; p++) {
                int m0 = u * 8 + p * 2;
                acc2 += bf_lo(wv[p]) * s_z[m0 * 4 + o] + bf_hi(wv[p]) * s_z[(m0 + 1) * 4 + o];
            }
        }
        s_flat[tid] = fmaxf(acc2 + b2[o], 0.f);
    } else {
        s_flat[tid] = 0.f;
    }
    __syncthreads();

    // r = relu(flat @ Wr1 + br1): warp w handles j = w*4..w*4+3; 32 lanes read
    // one 2KB row of Wr1^T coalesced (float4) and shfl-reduce.
    {
        const float4* fl4 = (const float4*)s_flat;   // 128 float4
        #pragma unroll
        for (int jj = 0; jj < 4; ++jj) {
            int j = warp * 4 + jj;
            const float4* wrow = (const float4*)(g_wr1t + (size_t)j * 512);
            float a = 0.f;
            #pragma unroll
            for (int u = 0; u < 4; ++u) {
                float4 w4 = wrow[lane + u * 32];
                float4 f4 = fl4[lane + u * 32];
                a += w4.x * f4.x + w4.y * f4.y + w4.z * f4.z + w4.w * f4.w;
            }
            a += __shfl_xor_sync(0xffffffffu, a, 16);
            a += __shfl_xor_sync(0xffffffffu, a, 8);
            a += __shfl_xor_sync(0xffffffffu, a, 4);
            a += __shfl_xor_sync(0xffffffffu, a, 2);
            a += __shfl_xor_sync(0xffffffffu, a, 1);
            if (lane == 0) s_r[j] = fmaxf(a + br1[j], 0.f);
        }
    }
    __syncthreads();

    // logits = r @ Wr2 + br2 ; log_softmax (2 classes)
    if (tid < 64) {
        float rv = s_r[tid];
        float p0 = rv * Wr2[tid * 2 + 0];
        float p1 = rv * Wr2[tid * 2 + 1];
        #pragma unroll
        for (int m = 16; m >= 1; m >>= 1) {
            p0 += __shfl_xor_sync(0xffffffffu, p0, m);
            p1 += __shfl_xor_sync(0xffffffffu, p1, m);
        }
        if ((tid & 31) == 0) {
            s_red[(tid >> 5) * 2 + 0] = p0;
            s_red[(tid >> 5) * 2 + 1] = p1;
        }
    }
    __syncthreads();
    if (tid == 0) {
        float l0 = s_red[0] + s_red[2] + br2[0];
        float l1 = s_red[1] + s_red[3] + br2[1];
        float mx = fmaxf(l0, l1);
        float lse = mx + logf(expf(l0 - mx) + expf(l1 - mx));
        out[(size_t)b * 2 + 0] = l0 - lse;
        out[(size_t)b * 2 + 1] = l1 - lse;
    }
}

extern "C" void kernel_launch(void* const* d_in, const int* in_sizes, int n_in,
                              void* d_out, int out_size) {
    const float* x   = (const float*)d_in[0];
    const float* sup = (const float*)d_in[1];
    const float* W1  = (const float*)d_in[2];
    const float* b1  = (const float*)d_in[3];
    const float* W2  = (const float*)d_in[4];
    const float* b2  = (const float*)d_in[5];
    const float* Wr1 = (const float*)d_in[6];
    const float* br1 = (const float*)d_in[7];
    const float* Wr2 = (const float*)d_in[8];
    const float* br2 = (const float*)d_in[9];
    float* out = (float*)d_out;

    int B = in_sizes[0] / (NN * FIN);

    prep_weights<<<(16384 + 64 * 512 + 255) / 256, 256>>>(W1, Wr1);

    cudaFuncSetAttribute(gcn_mma, cudaFuncAttributeMaxDynamicSharedMemorySize, SMEM_BYTES);
    gcn_mma<<<B, NTHR, SMEM_BYTES>>>(x, sup, W1, b1, W2, b2, Wr1, br1, Wr2, br2, out);
}